// round 1
// baseline (speedup 1.0000x reference)
#include <cuda_runtime.h>

// ConditionalARNet: per-sample 9-node GCN + context MLP + 3-layer per-position MLP.
// One thread = one (sample, spatial position p in [0,63)). 4 samples / 256-thread block.
// Heavy 64x64 layer done with packed fma.rn.f32x2 (2 FMAs/instr), W2 broadcast from SMEM.

#define SPB 4  // samples per block

__device__ __forceinline__ unsigned long long pk2(float lo, float hi) {
    unsigned long long r;
    asm("mov.b64 %0, {%1, %2};" : "=l"(r) : "f"(lo), "f"(hi));
    return r;
}
__device__ __forceinline__ float2 upk2(unsigned long long v) {
    float2 f;
    asm("mov.b64 {%0, %1}, %2;" : "=f"(f.x), "=f"(f.y) : "l"(v));
    return f;
}
__device__ __forceinline__ unsigned long long fma2(unsigned long long a,
                                                   unsigned long long b,
                                                   unsigned long long c) {
    unsigned long long d;
    asm("fma.rn.f32x2 %0, %1, %2, %3;" : "=l"(d) : "l"(a), "l"(b), "l"(c));
    return d;
}
__device__ __forceinline__ unsigned long long add2(unsigned long long a,
                                                   unsigned long long b) {
    unsigned long long d;
    asm("add.rn.f32x2 %0, %1, %2;" : "=l"(d) : "l"(a), "l"(b));
    return d;
}

// np.triu_indices(9) row/col tables
__constant__ unsigned char c_iu_i[45] = {
    0,0,0,0,0,0,0,0,0,
    1,1,1,1,1,1,1,1,
    2,2,2,2,2,2,2,
    3,3,3,3,3,3,
    4,4,4,4,4,
    5,5,5,5,
    6,6,6,
    7,7,
    8};
__constant__ unsigned char c_iu_j[45] = {
    0,1,2,3,4,5,6,7,8,
    1,2,3,4,5,6,7,8,
    2,3,4,5,6,7,8,
    3,4,5,6,7,8,
    4,5,6,7,8,
    5,6,7,8,
    6,7,8,
    7,8,
    8};

__global__ __launch_bounds__(256, 2)
void car_kernel(const float* __restrict__ x,      // (B,1,9,7)
                const int*   __restrict__ adj,    // (B,45)
                const float* __restrict__ ctx,    // (B,1,9,5) -> 45 floats
                const float* __restrict__ gcnW,   // (7,7)
                const float* __restrict__ gcnB,   // (7,)
                const float* __restrict__ ctxW,   // (45,63)
                const float* __restrict__ ctxB,   // (63,)
                const float* __restrict__ W1,     // (64,2)
                const float* __restrict__ b1,     // (64,)
                const float* __restrict__ W2,     // (64,64)
                const float* __restrict__ b2,     // (64,)
                const float* __restrict__ W3,     // (2,64)
                const float* __restrict__ b3,     // (2,)
                float* __restrict__ out,          // (B,2,9,7)
                int Bn)
{
    __shared__ __align__(16) float sW2[4096];
    __shared__ float sCtxW[2835];
    __shared__ float sW1[128], sB1[64], sB2[64], sW3[128];
    __shared__ float sGW[49], sGB[7], sCB[63], sB3[2];
    __shared__ float sx[SPB][64];
    __shared__ float sy[SPB][64];
    __shared__ float sA[SPB][81];
    __shared__ float sd[SPB][9];
    __shared__ float sctx[SPB][48];

    const int tid = threadIdx.x;
    const int grp = tid >> 6;
    const int g   = tid & 63;
    const int s   = blockIdx.x * SPB + grp;
    const bool valid = (s < Bn);

    // ---- phase 1: cooperative loads + zero A ----
    for (int i = tid; i < 4096; i += 256) sW2[i] = W2[i];
    for (int i = tid; i < 2835; i += 256) sCtxW[i] = ctxW[i];
    if (tid < 128) { sW1[tid] = W1[tid]; sW3[tid] = W3[tid]; }
    if (tid < 64)  { sB1[tid] = b1[tid]; sB2[tid] = b2[tid]; }
    if (tid < 49)  sGW[tid] = gcnW[tid];
    if (tid < 7)   sGB[tid] = gcnB[tid];
    if (tid < 63)  sCB[tid] = ctxB[tid];
    if (tid < 2)   sB3[tid] = b3[tid];

    sA[grp][g] = 0.f;
    if (g < 17) sA[grp][g + 64] = 0.f;
    if (valid) {
        if (g < 63) sx[grp][g]   = x[s * 63 + g];
        if (g < 45) sctx[grp][g] = ctx[s * 45 + g];
    }
    __syncthreads();

    // ---- phase 2: upper-tri adjacency fill (NOT symmetrized, matches ref) + y = x @ gcnW ----
    if (valid && g < 45) {
        int i = c_iu_i[g], j = c_iu_j[g];
        sA[grp][i * 9 + j] = (adj[s * 45 + g] > 0) ? 1.f : 0.f;
    }
    if (g < 63) {
        int n = g / 7, f = g % 7;
        float acc = 0.f;
        #pragma unroll
        for (int k = 0; k < 7; ++k)
            acc = fmaf(sx[grp][n * 7 + k], sGW[k * 7 + f], acc);
        sy[grp][g] = acc;
    }
    __syncthreads();

    // ---- phase 3: force diag=1, row sums -> d = rsqrt(max(sum,1)) ----
    if (g < 9) {
        sA[grp][g * 9 + g] = 1.f;
        float rs = 0.f;
        #pragma unroll
        for (int m = 0; m < 9; ++m) rs += sA[grp][g * 9 + m];
        rs = fmaxf(rs, 1.f);   // diag forces >=1 anyway
        sd[grp][g] = rsqrtf(rs);
    }
    __syncthreads();

    // ---- phase 4: per-position compute ----
    if (g < 63) {
        const int n = g / 7, f = g % 7;

        // z_p = d[n] * sum_m A[n,m] * d[m] * y[m,f] + gcnB[f]
        float zp = 0.f;
        #pragma unroll
        for (int m = 0; m < 9; ++m)
            zp = fmaf(sA[grp][n * 9 + m] * sd[grp][m], sy[grp][m * 7 + f], zp);
        zp = fmaf(zp, sd[grp][n], sGB[f]);

        // c_p = relu(ctx . ctxW[:,p] + ctxB[p])
        float cp = sCB[g];
        #pragma unroll 5
        for (int i = 0; i < 45; ++i)
            cp = fmaf(sctx[grp][i], sCtxW[i * 63 + g], cp);
        cp = fmaxf(cp, 0.f);

        // h1 = relu(W1 @ [z;c] + b1), packed as 32 f32x2 pairs
        unsigned long long h1p[32];
        #pragma unroll
        for (int j = 0; j < 32; ++j) {
            int o0 = 2 * j, o1 = 2 * j + 1;
            float a = fmaf(zp, sW1[2 * o0], fmaf(cp, sW1[2 * o0 + 1], sB1[o0]));
            float b = fmaf(zp, sW1[2 * o1], fmaf(cp, sW1[2 * o1 + 1], sB1[o1]));
            h1p[j] = pk2(fmaxf(a, 0.f), fmaxf(b, 0.f));
        }

        // layer2 (64x64, f32x2 packed) with fused layer3 epilogue
        float out0 = sB3[0];
        float out1 = sB3[1];
        #pragma unroll 4
        for (int o = 0; o < 64; ++o) {
            const ulonglong2* wrow = (const ulonglong2*)(sW2 + (o << 6));
            unsigned long long a0 = 0ull, a1 = 0ull, a2 = 0ull, a3 = 0ull;
            #pragma unroll
            for (int k = 0; k < 8; ++k) {
                ulonglong2 wA = wrow[2 * k];
                ulonglong2 wB = wrow[2 * k + 1];
                a0 = fma2(wA.x, h1p[4 * k + 0], a0);
                a1 = fma2(wA.y, h1p[4 * k + 1], a1);
                a2 = fma2(wB.x, h1p[4 * k + 2], a2);
                a3 = fma2(wB.y, h1p[4 * k + 3], a3);
            }
            a0 = add2(a0, a1);
            a2 = add2(a2, a3);
            a0 = add2(a0, a2);
            float2 fv = upk2(a0);
            float h2o = fmaxf(fv.x + fv.y + sB2[o], 0.f);
            out0 = fmaf(sW3[o],      h2o, out0);
            out1 = fmaf(sW3[64 + o], h2o, out1);
        }

        if (valid) {
            out[s * 126 + g]      = out0;
            out[s * 126 + 63 + g] = out1;
        }
    }
}

extern "C" void kernel_launch(void* const* d_in, const int* in_sizes, int n_in,
                              void* d_out, int out_size) {
    const float* x    = (const float*)d_in[0];
    const int*   adj  = (const int*)  d_in[1];
    const float* ctx  = (const float*)d_in[2];
    const float* gcnW = (const float*)d_in[3];
    const float* gcnB = (const float*)d_in[4];
    const float* ctxW = (const float*)d_in[5];
    const float* ctxB = (const float*)d_in[6];
    const float* W1   = (const float*)d_in[7];
    const float* b1   = (const float*)d_in[8];
    const float* W2   = (const float*)d_in[9];
    const float* b2   = (const float*)d_in[10];
    const float* W3   = (const float*)d_in[11];
    const float* b3   = (const float*)d_in[12];
    float* out = (float*)d_out;

    int Bn = in_sizes[0] / 63;
    int grid = (Bn + SPB - 1) / SPB;
    car_kernel<<<grid, 256>>>(x, adj, ctx, gcnW, gcnB, ctxW, ctxB,
                              W1, b1, W2, b2, W3, b3, out, Bn);
}

// round 4
// speedup vs baseline: 1.2346x; 1.2346x over previous
#include <cuda_runtime.h>
#include <cuda_bf16.h>
#include <cstdint>

// ============================================================
// Plain-sm_103-compatible tensor path: ldmatrix + mma.sync (bf16)
// ============================================================

__device__ __forceinline__ uint32_t smem_u32(const void* p) {
    uint32_t a;
    asm("{ .reg .u64 t; cvta.to.shared.u64 t, %1; cvt.u32.u64 %0, t; }" : "=r"(a) : "l"(p));
    return a;
}

__device__ __forceinline__ void ldsm4(uint32_t r[4], uint32_t addr) {
    asm volatile("ldmatrix.sync.aligned.m8n8.x4.shared.b16 {%0,%1,%2,%3}, [%4];"
                 : "=r"(r[0]), "=r"(r[1]), "=r"(r[2]), "=r"(r[3]) : "r"(addr));
}

__device__ __forceinline__ void mma16816(float c[4], const uint32_t a[4],
                                          uint32_t b0, uint32_t b1) {
    asm volatile("mma.sync.aligned.m16n8k16.row.col.f32.bf16.bf16.f32 "
                 "{%0,%1,%2,%3}, {%4,%5,%6,%7}, {%8,%9}, {%0,%1,%2,%3};"
                 : "+f"(c[0]), "+f"(c[1]), "+f"(c[2]), "+f"(c[3])
                 : "r"(a[0]), "r"(a[1]), "r"(a[2]), "r"(a[3]), "r"(b0), "r"(b1));
}

// triu(9) index tables
__constant__ unsigned char c_iu_i[45] = {
    0,0,0,0,0,0,0,0,0, 1,1,1,1,1,1,1,1, 2,2,2,2,2,2,2,
    3,3,3,3,3,3, 4,4,4,4,4, 5,5,5,5, 6,6,6, 7,7, 8};
__constant__ unsigned char c_iu_j[45] = {
    0,1,2,3,4,5,6,7,8, 1,2,3,4,5,6,7,8, 2,3,4,5,6,7,8,
    3,4,5,6,7,8, 4,5,6,7,8, 5,6,7,8, 6,7,8, 7,8, 8};

// ---- shared memory layout (dynamic, 110592 bytes requested) ----
#define OFF_BHI   0
#define OFF_BLO   9216
#define OFF_AHI   18432
#define OFF_ALO   55296
#define OFF_F     92160
#define SMEM_BYTES 110592

#define LDAB 72   // bf16 row stride for A and B tiles
#define LDH2 66   // float row stride for epilogue h2 buffer

// float misc region offsets (in floats)
#define F_CTXW 0       // 2835
#define F_W1   2835    // 128
#define F_B1   2963    // 64
#define F_B2   3027    // 64
#define F_W3   3091    // 128
#define F_GW   3219    // 49
#define F_GB   3268    // 7
#define F_CB   3275    // 63
#define F_B3   3338    // 2
#define F_X    3340    // 4*63
#define F_Y    3592    // 4*63
#define F_ADJ  3844    // 4*81
#define F_D    4168    // 4*9
#define F_CTX  4204    // 4*45  (end 4384)

__global__ __launch_bounds__(256, 2)
void car_mma_kernel(const float* __restrict__ x,      // (B,1,9,7)
                    const int*   __restrict__ adj,    // (B,45)
                    const float* __restrict__ ctx,    // (B,1,9,5)
                    const float* __restrict__ gcnW,   // (7,7)
                    const float* __restrict__ gcnB,   // (7,)
                    const float* __restrict__ ctxW,   // (45,63)
                    const float* __restrict__ ctxB,   // (63,)
                    const float* __restrict__ W1,     // (64,2)
                    const float* __restrict__ b1,     // (64,)
                    const float* __restrict__ W2,     // (64,64)
                    const float* __restrict__ b2,     // (64,)
                    const float* __restrict__ W3,     // (2,64)
                    const float* __restrict__ b3,     // (2,)
                    float* __restrict__ out,          // (B,2,9,7)
                    int Bn)
{
    extern __shared__ __align__(16) char sm[];
    __nv_bfloat16* sBhi = (__nv_bfloat16*)(sm + OFF_BHI);
    __nv_bfloat16* sBlo = (__nv_bfloat16*)(sm + OFF_BLO);
    __nv_bfloat16* sAhi = (__nv_bfloat16*)(sm + OFF_AHI);
    __nv_bfloat16* sAlo = (__nv_bfloat16*)(sm + OFF_ALO);
    float* sF = (float*)(sm + OFF_F);

    const int tid  = threadIdx.x;
    const int wid  = tid >> 5;
    const int lane = tid & 31;

    // ---- phase 1: weights -> SMEM; W2 -> bf16 hi/lo tiles ----
    for (int i = tid; i < 4096; i += 256) {
        float w = W2[i];                 // W2[n=o][k=c], k contiguous
        __nv_bfloat16 hi = __float2bfloat16(w);
        __nv_bfloat16 lo = __float2bfloat16(w - __bfloat162float(hi));
        int n = i >> 6, k = i & 63;
        sBhi[n * LDAB + k] = hi;
        sBlo[n * LDAB + k] = lo;
    }
    for (int i = tid; i < 2835; i += 256) sF[F_CTXW + i] = ctxW[i];
    if (tid < 128) { sF[F_W1 + tid] = W1[tid]; sF[F_W3 + tid] = W3[tid]; }
    if (tid < 64)  { sF[F_B1 + tid] = b1[tid]; sF[F_B2 + tid] = b2[tid]; }
    if (tid < 49)  sF[F_GW + tid] = gcnW[tid];
    if (tid < 7)   sF[F_GB + tid] = gcnB[tid];
    if (tid < 63)  sF[F_CB + tid] = ctxB[tid];
    if (tid < 2)   sF[F_B3 + tid] = b3[tid];

    // per-sample staging: 4 samples / CTA
    const int grp = tid >> 6;
    const int g64 = tid & 63;
    const int sG  = blockIdx.x * 4 + grp;
    const bool svalid = (sG < Bn);
    // zero ALL 81 adjacency entries (g64 only spans [0,64) -> need second line)
    sF[F_ADJ + grp * 81 + g64] = 0.f;
    if (g64 < 17) sF[F_ADJ + grp * 81 + 64 + g64] = 0.f;
    if (g64 < 63) sF[F_X + grp * 63 + g64] = svalid ? x[sG * 63 + g64] : 0.f;
    if (g64 < 45) sF[F_CTX + grp * 45 + g64] = svalid ? ctx[sG * 45 + g64] : 0.f;
    __syncthreads();

    // ---- phase 2: adjacency fill + y = x @ gcnW ----
    if (svalid && g64 < 45) {
        int i = c_iu_i[g64], j = c_iu_j[g64];
        sF[F_ADJ + grp * 81 + i * 9 + j] = (adj[sG * 45 + g64] > 0) ? 1.f : 0.f;
    }
    if (g64 < 63) {
        int n = g64 / 7, f = g64 % 7;
        float acc = 0.f;
        #pragma unroll
        for (int k = 0; k < 7; ++k)
            acc = fmaf(sF[F_X + grp * 63 + n * 7 + k], sF[F_GW + k * 7 + f], acc);
        sF[F_Y + grp * 63 + g64] = acc;
    }
    __syncthreads();

    // ---- phase 3: diag=1, degree norm ----
    if (g64 < 9) {
        sF[F_ADJ + grp * 81 + g64 * 9 + g64] = 1.f;
        float rs = 0.f;
        #pragma unroll
        for (int m = 0; m < 9; ++m) rs += sF[F_ADJ + grp * 81 + g64 * 9 + m];
        sF[F_D + grp * 9 + g64] = rsqrtf(fmaxf(rs, 1.f));
    }
    __syncthreads();

    // ---- phase 4: per-position h1, bf16 hi/lo rows into SMEM A ----
    {
        const int sl = tid / 63;
        const int g  = tid - sl * 63;
        const bool pvalid = (tid < 252) && (blockIdx.x * 4 + sl < Bn);
        float zp = 0.f, cp = 0.f;
        if (pvalid) {
            const int n = g / 7, f = g % 7;
            #pragma unroll
            for (int m = 0; m < 9; ++m)
                zp = fmaf(sF[F_ADJ + sl * 81 + n * 9 + m] * sF[F_D + sl * 9 + m],
                          sF[F_Y + sl * 63 + m * 7 + f], zp);
            zp = fmaf(zp, sF[F_D + sl * 9 + n], sF[F_GB + f]);
            cp = sF[F_CB + g];
            #pragma unroll 5
            for (int i = 0; i < 45; ++i)
                cp = fmaf(sF[F_CTX + sl * 45 + i], sF[F_CTXW + i * 63 + g], cp);
            cp = fmaxf(cp, 0.f);
        }
        uint32_t* rowHi = (uint32_t*)(sAhi + tid * LDAB);
        uint32_t* rowLo = (uint32_t*)(sAlo + tid * LDAB);
        #pragma unroll
        for (int j = 0; j < 32; ++j) {
            int o0 = 2 * j, o1 = 2 * j + 1;
            float a = fmaxf(fmaf(zp, sF[F_W1 + 2 * o0], fmaf(cp, sF[F_W1 + 2 * o0 + 1], sF[F_B1 + o0])), 0.f);
            float b = fmaxf(fmaf(zp, sF[F_W1 + 2 * o1], fmaf(cp, sF[F_W1 + 2 * o1 + 1], sF[F_B1 + o1])), 0.f);
            if (!pvalid) { a = 0.f; b = 0.f; }
            __nv_bfloat16 ah = __float2bfloat16(a);
            __nv_bfloat16 bh = __float2bfloat16(b);
            __nv_bfloat162 hp; hp.x = ah; hp.y = bh;
            __nv_bfloat162 lp = __floats2bfloat162_rn(a - __bfloat162float(ah),
                                                      b - __bfloat162float(bh));
            rowHi[j] = *reinterpret_cast<uint32_t*>(&hp);
            rowLo[j] = *reinterpret_cast<uint32_t*>(&lp);
        }
    }
    __syncthreads();

    // ---- phase 5: per-warp HMMA GEMM: C[32x64] = A[32x64] * W2^T ----
    float C[2][8][4];
    #pragma unroll
    for (int m = 0; m < 2; ++m)
        #pragma unroll
        for (int n = 0; n < 8; ++n)
            #pragma unroll
            for (int q = 0; q < 4; ++q) C[m][n][q] = 0.f;

    {
        const uint32_t sub = (uint32_t)(lane >> 3);
        const uint32_t j7  = (uint32_t)(lane & 7);
        const uint32_t aOff = ((sub & 1) * 8 + j7) * (LDAB * 2) + (sub >> 1) * 16;
        const uint32_t aHiBase = smem_u32(sAhi) + (uint32_t)(wid * 32) * (LDAB * 2) + aOff;
        const uint32_t aLoBase = smem_u32(sAlo) + (uint32_t)(wid * 32) * (LDAB * 2) + aOff;
        const uint32_t bOff = ((sub >> 1) * 8 + j7) * (LDAB * 2) + (sub & 1) * 16;
        const uint32_t bHiBase = smem_u32(sBhi) + bOff;
        const uint32_t bLoBase = smem_u32(sBlo) + bOff;

        #pragma unroll
        for (int ks = 0; ks < 4; ++ks) {
            const uint32_t kB = (uint32_t)ks * 32;  // 16 bf16 = 32 bytes
            uint32_t ah[2][4], al[2][4];
            ldsm4(ah[0], aHiBase + kB);
            ldsm4(ah[1], aHiBase + 16 * (LDAB * 2) + kB);
            ldsm4(al[0], aLoBase + kB);
            ldsm4(al[1], aLoBase + 16 * (LDAB * 2) + kB);
            #pragma unroll
            for (int nh = 0; nh < 2; ++nh) {
                uint32_t bh[2][4], bl[2][4];
                ldsm4(bh[0], bHiBase + (uint32_t)(nh * 32)      * (LDAB * 2) + kB);
                ldsm4(bh[1], bHiBase + (uint32_t)(nh * 32 + 16) * (LDAB * 2) + kB);
                ldsm4(bl[0], bLoBase + (uint32_t)(nh * 32)      * (LDAB * 2) + kB);
                ldsm4(bl[1], bLoBase + (uint32_t)(nh * 32 + 16) * (LDAB * 2) + kB);
                #pragma unroll
                for (int m = 0; m < 2; ++m) {
                    #pragma unroll
                    for (int t = 0; t < 4; ++t) {
                        const int nt = nh * 4 + t;
                        const uint32_t b0h = bh[t >> 1][(t & 1) * 2];
                        const uint32_t b1h = bh[t >> 1][(t & 1) * 2 + 1];
                        const uint32_t b0l = bl[t >> 1][(t & 1) * 2];
                        const uint32_t b1l = bl[t >> 1][(t & 1) * 2 + 1];
                        mma16816(C[m][nt], ah[m], b0h, b1h);   // hi*hi
                        mma16816(C[m][nt], ah[m], b0l, b1l);   // hi*lo
                        mma16816(C[m][nt], al[m], b0h, b1h);   // lo*hi
                    }
                }
            }
        }
    }
    __syncthreads();   // all ldmatrix reads done; safe to reuse A region

    // ---- phase 6: C -> SMEM h2 buffer (reuse A region) ----
    {
        float* sH2 = (float*)(sm + OFF_AHI);
        const int rbase = wid * 32 + (lane >> 2);
        const int cbase = (lane & 3) * 2;
        #pragma unroll
        for (int m = 0; m < 2; ++m) {
            #pragma unroll
            for (int n = 0; n < 8; ++n) {
                const int r = rbase + m * 16;
                const int c = n * 8 + cbase;
                *(float2*)(sH2 + r * LDH2 + c)       = make_float2(C[m][n][0], C[m][n][1]);
                *(float2*)(sH2 + (r + 8) * LDH2 + c) = make_float2(C[m][n][2], C[m][n][3]);
            }
        }
    }
    __syncthreads();

    // ---- phase 7: per-position relu+bias + layer-3 epilogue ----
    {
        const float* sH2 = (const float*)(sm + OFF_AHI);
        const int sl = tid / 63;
        const int g  = tid - sl * 63;
        const int sO = blockIdx.x * 4 + sl;
        if (tid < 252 && sO < Bn) {
            const float* row = sH2 + tid * LDH2;
            float out0 = sF[F_B3 + 0], out1 = sF[F_B3 + 1];
            #pragma unroll
            for (int c = 0; c < 64; ++c) {
                float h2 = fmaxf(row[c] + sF[F_B2 + c], 0.f);
                out0 = fmaf(sF[F_W3 + c],      h2, out0);
                out1 = fmaf(sF[F_W3 + 64 + c], h2, out1);
            }
            out[sO * 126 + g]      = out0;
            out[sO * 126 + 63 + g] = out1;
        }
    }
}

extern "C" void kernel_launch(void* const* d_in, const int* in_sizes, int n_in,
                              void* d_out, int out_size) {
    const float* x    = (const float*)d_in[0];
    const int*   adj  = (const int*)  d_in[1];
    const float* ctx  = (const float*)d_in[2];
    const float* gcnW = (const float*)d_in[3];
    const float* gcnB = (const float*)d_in[4];
    const float* ctxW = (const float*)d_in[5];
    const float* ctxB = (const float*)d_in[6];
    const float* W1   = (const float*)d_in[7];
    const float* b1   = (const float*)d_in[8];
    const float* W2   = (const float*)d_in[9];
    const float* b2   = (const float*)d_in[10];
    const float* W3   = (const float*)d_in[11];
    const float* b3   = (const float*)d_in[12];
    float* outp = (float*)d_out;

    cudaFuncSetAttribute(car_mma_kernel,
                         cudaFuncAttributeMaxDynamicSharedMemorySize, SMEM_BYTES);

    int Bn = in_sizes[0] / 63;
    int grid = (Bn + 3) / 4;
    car_mma_kernel<<<grid, 256, SMEM_BYTES>>>(x, adj, ctx, gcnW, gcnB, ctxW, ctxB,
                                              W1, b1, W2, b2, W3, b3, outp, Bn);
}

// round 5
// speedup vs baseline: 1.6917x; 1.3702x over previous
#include <cuda_runtime.h>
#include <cuda_bf16.h>
#include <cstdint>

// ============================================================
// ldmatrix(B only) + mma.sync bf16 3-term split; A fragments built in registers.
// CTA = 256 threads, 2 samples (M=128 rows, 126 valid), 8 warps x 16 rows.
// ============================================================

__device__ __forceinline__ uint32_t smem_u32(const void* p) {
    uint32_t a;
    asm("{ .reg .u64 t; cvta.to.shared.u64 t, %1; cvt.u32.u64 %0, t; }" : "=r"(a) : "l"(p));
    return a;
}

__device__ __forceinline__ void ldsm4(uint32_t r[4], uint32_t addr) {
    asm volatile("ldmatrix.sync.aligned.m8n8.x4.shared.b16 {%0,%1,%2,%3}, [%4];"
                 : "=r"(r[0]), "=r"(r[1]), "=r"(r[2]), "=r"(r[3]) : "r"(addr));
}

__device__ __forceinline__ void mma16816(float c[4], const uint32_t a[4],
                                          uint32_t b0, uint32_t b1) {
    asm volatile("mma.sync.aligned.m16n8k16.row.col.f32.bf16.bf16.f32 "
                 "{%0,%1,%2,%3}, {%4,%5,%6,%7}, {%8,%9}, {%0,%1,%2,%3};"
                 : "+f"(c[0]), "+f"(c[1]), "+f"(c[2]), "+f"(c[3])
                 : "r"(a[0]), "r"(a[1]), "r"(a[2]), "r"(a[3]), "r"(b0), "r"(b1));
}

__device__ __forceinline__ void split_pack(float a, float b, uint32_t& hi, uint32_t& lo) {
    __nv_bfloat16 ah = __float2bfloat16(a);
    __nv_bfloat16 bh = __float2bfloat16(b);
    __nv_bfloat162 hp; hp.x = ah; hp.y = bh;
    __nv_bfloat162 lp = __floats2bfloat162_rn(a - __bfloat162float(ah),
                                              b - __bfloat162float(bh));
    hi = *reinterpret_cast<uint32_t*>(&hp);
    lo = *reinterpret_cast<uint32_t*>(&lp);
}

// triu(9) index tables
__constant__ unsigned char c_iu_i[45] = {
    0,0,0,0,0,0,0,0,0, 1,1,1,1,1,1,1,1, 2,2,2,2,2,2,2,
    3,3,3,3,3,3, 4,4,4,4,4, 5,5,5,5, 6,6,6, 7,7, 8};
__constant__ unsigned char c_iu_j[45] = {
    0,1,2,3,4,5,6,7,8, 1,2,3,4,5,6,7,8, 2,3,4,5,6,7,8,
    3,4,5,6,7,8, 4,5,6,7,8, 5,6,7,8, 6,7,8, 7,8, 8};

#define LDAB 72   // bf16 row stride for B tiles (144 B)

// float misc region offsets
#define F_CTXW 0       // 2835
#define F_W1   2835    // 128
#define F_B1   2963    // 64
#define F_B2   3027    // 64
#define F_W3   3091    // 128
#define F_GW   3219    // 49
#define F_GB   3268    // 7
#define F_CB   3275    // 63
#define F_B3   3338    // 2
#define F_X    3340    // 2*63
#define F_Y    3466    // 2*63
#define F_ADJ  3592    // 2*81
#define F_D    3754    // 2*9
#define F_CTX  3772    // 2*45
#define F_TOTAL 3862

__global__ __launch_bounds__(256, 3)
void car_mma2_kernel(const float* __restrict__ x,      // (B,1,9,7)
                     const int*   __restrict__ adj,    // (B,45)
                     const float* __restrict__ ctx,    // (B,1,9,5)
                     const float* __restrict__ gcnW,   // (7,7)
                     const float* __restrict__ gcnB,   // (7,)
                     const float* __restrict__ ctxW,   // (45,63)
                     const float* __restrict__ ctxB,   // (63,)
                     const float* __restrict__ W1,     // (64,2)
                     const float* __restrict__ b1,     // (64,)
                     const float* __restrict__ W2,     // (64,64)
                     const float* __restrict__ b2,     // (64,)
                     const float* __restrict__ W3,     // (2,64)
                     const float* __restrict__ b3,     // (2,)
                     float* __restrict__ out,          // (B,2,9,7)
                     int Bn)
{
    __shared__ __align__(16) __nv_bfloat16 sBhi[64 * LDAB];
    __shared__ __align__(16) __nv_bfloat16 sBlo[64 * LDAB];
    __shared__ float sF[F_TOTAL];

    const int tid  = threadIdx.x;
    const int wid  = tid >> 5;
    const int lane = tid & 31;

    // ---- phase 1: weights -> SMEM; W2 -> bf16 hi/lo tiles ----
    for (int i = tid; i < 4096; i += 256) {
        float w = W2[i];                 // W2[n=o][k=c], k contiguous
        __nv_bfloat16 hi = __float2bfloat16(w);
        __nv_bfloat16 lo = __float2bfloat16(w - __bfloat162float(hi));
        int n = i >> 6, k = i & 63;
        sBhi[n * LDAB + k] = hi;
        sBlo[n * LDAB + k] = lo;
    }
    for (int i = tid; i < 2835; i += 256) sF[F_CTXW + i] = ctxW[i];
    if (tid < 128) { sF[F_W1 + tid] = W1[tid]; sF[F_W3 + tid] = W3[tid]; }
    if (tid < 64)  { sF[F_B1 + tid] = b1[tid]; sF[F_B2 + tid] = b2[tid]; }
    if (tid < 49)  sF[F_GW + tid] = gcnW[tid];
    if (tid < 7)   sF[F_GB + tid] = gcnB[tid];
    if (tid < 63)  sF[F_CB + tid] = ctxB[tid];
    if (tid < 2)   sF[F_B3 + tid] = b3[tid];

    // per-sample staging: 2 samples / CTA
    const int grp   = tid >> 7;      // 0..1
    const int inner = tid & 127;
    const int sG    = blockIdx.x * 2 + grp;
    const bool svalid = (sG < Bn);
    if (inner < 81) sF[F_ADJ + grp * 81 + inner] = 0.f;
    if (inner < 63) sF[F_X + grp * 63 + inner] = svalid ? x[sG * 63 + inner] : 0.f;
    if (inner < 45) sF[F_CTX + grp * 45 + inner] = svalid ? ctx[sG * 45 + inner] : 0.f;
    __syncthreads();

    // ---- phase 2: adjacency fill + y = x @ gcnW ----
    if (svalid && inner < 45) {
        int i = c_iu_i[inner], j = c_iu_j[inner];
        sF[F_ADJ + grp * 81 + i * 9 + j] = (adj[sG * 45 + inner] > 0) ? 1.f : 0.f;
    }
    if (inner < 63) {
        int n = inner / 7, f = inner % 7;
        float acc = 0.f;
        #pragma unroll
        for (int k = 0; k < 7; ++k)
            acc = fmaf(sF[F_X + grp * 63 + n * 7 + k], sF[F_GW + k * 7 + f], acc);
        sF[F_Y + grp * 63 + inner] = acc;
    }
    __syncthreads();

    // ---- phase 3: diag=1, degree norm ----
    if (inner < 9) {
        sF[F_ADJ + grp * 81 + inner * 9 + inner] = 1.f;
        float rs = 0.f;
        #pragma unroll
        for (int m = 0; m < 9; ++m) rs += sF[F_ADJ + grp * 81 + inner * 9 + m];
        sF[F_D + grp * 9 + inner] = rsqrtf(fmaxf(rs, 1.f));
    }
    __syncthreads();

    // ---- phase 4: per-lane zp/cp for its two fragment rows ----
    const int l4  = lane >> 2;
    const int lm4 = lane & 3;
    const int r0  = wid * 16 + l4;     // rows r0, r0+8 within M=128

    float zp[2], cp[2];
    #pragma unroll
    for (int e = 0; e < 2; ++e) {
        const int row = r0 + 8 * e;
        const int sl  = row >> 6;
        const int g   = row & 63;
        const bool pv = (g < 63) && (blockIdx.x * 2 + sl < Bn);
        float z = 0.f, c = 0.f;
        if (pv) {
            const int n = g / 7, f = g % 7;
            float acc = 0.f;
            #pragma unroll
            for (int m = 0; m < 9; ++m)
                acc = fmaf(sF[F_ADJ + sl * 81 + n * 9 + m] * sF[F_D + sl * 9 + m],
                           sF[F_Y + sl * 63 + m * 7 + f], acc);
            z = fmaf(acc, sF[F_D + sl * 9 + n], sF[F_GB + f]);
            float a0 = 0.f, a1 = 0.f, a2 = 0.f, a3 = 0.f;
            const float* cw = sF + F_CTXW + g;
            const float* cx = sF + F_CTX + sl * 45;
            #pragma unroll
            for (int i = 0; i < 44; i += 4) {
                a0 = fmaf(cx[i],     cw[i * 63],       a0);
                a1 = fmaf(cx[i + 1], cw[(i + 1) * 63], a1);
                a2 = fmaf(cx[i + 2], cw[(i + 2) * 63], a2);
                a3 = fmaf(cx[i + 3], cw[(i + 3) * 63], a3);
            }
            a0 = fmaf(cx[44], cw[44 * 63], a0);
            c = fmaxf(sF[F_CB + g] + ((a0 + a1) + (a2 + a3)), 0.f);
        }
        zp[e] = z; cp[e] = c;
    }

    // ---- phase 5: k-loop, A fragments built in registers, HMMA ----
    float C[8][4];
    #pragma unroll
    for (int n = 0; n < 8; ++n)
        #pragma unroll
        for (int q = 0; q < 4; ++q) C[n][q] = 0.f;

    const uint32_t sub = (uint32_t)(lane >> 3);
    const uint32_t j7  = (uint32_t)(lane & 7);
    const uint32_t bOff = ((sub >> 1) * 8 + j7) * (LDAB * 2) + (sub & 1) * 16;
    const uint32_t bHiBase = smem_u32(sBhi) + bOff;
    const uint32_t bLoBase = smem_u32(sBlo) + bOff;

    #pragma unroll
    for (int ks = 0; ks < 4; ++ks) {
        // A fragments: rows r0, r0+8; cols cb,cb+1 (pair0), cb+8,cb+9 (pair1)
        uint32_t Ahi[4], Alo[4];
        const int cb = lm4 * 2 + ks * 16;
        #pragma unroll
        for (int p = 0; p < 2; ++p) {
            const int c = cb + p * 8;
            const float w00 = sF[F_W1 + 2 * c],     w01 = sF[F_W1 + 2 * c + 1];
            const float w10 = sF[F_W1 + 2 * c + 2], w11 = sF[F_W1 + 2 * c + 3];
            const float bb0 = sF[F_B1 + c],         bb1 = sF[F_B1 + c + 1];
            #pragma unroll
            for (int e = 0; e < 2; ++e) {
                float v0 = fmaxf(fmaf(zp[e], w00, fmaf(cp[e], w01, bb0)), 0.f);
                float v1 = fmaxf(fmaf(zp[e], w10, fmaf(cp[e], w11, bb1)), 0.f);
                split_pack(v0, v1, Ahi[p * 2 + e], Alo[p * 2 + e]);
            }
        }

        const uint32_t kB = (uint32_t)ks * 32;  // 16 bf16 = 32 bytes
        #pragma unroll
        for (int nh = 0; nh < 2; ++nh) {
            uint32_t bh[2][4], bl[2][4];
            ldsm4(bh[0], bHiBase + (uint32_t)(nh * 32)      * (LDAB * 2) + kB);
            ldsm4(bh[1], bHiBase + (uint32_t)(nh * 32 + 16) * (LDAB * 2) + kB);
            ldsm4(bl[0], bLoBase + (uint32_t)(nh * 32)      * (LDAB * 2) + kB);
            ldsm4(bl[1], bLoBase + (uint32_t)(nh * 32 + 16) * (LDAB * 2) + kB);
            #pragma unroll
            for (int t = 0; t < 4; ++t) {
                const int nt = nh * 4 + t;
                const uint32_t b0h = bh[t >> 1][(t & 1) * 2];
                const uint32_t b1h = bh[t >> 1][(t & 1) * 2 + 1];
                const uint32_t b0l = bl[t >> 1][(t & 1) * 2];
                const uint32_t b1l = bl[t >> 1][(t & 1) * 2 + 1];
                mma16816(C[nt], Ahi, b0h, b1h);   // hi*hi
                mma16816(C[nt], Ahi, b0l, b1l);   // hi*lo
                mma16816(C[nt], Alo, b0h, b1h);   // lo*hi
            }
        }
    }

    // ---- phase 6: in-register epilogue: relu+b2, W3 dot, quad reduce ----
    float o00 = 0.f, o01 = 0.f, o10 = 0.f, o11 = 0.f;  // (row e, out channel)
    #pragma unroll
    for (int nt = 0; nt < 8; ++nt) {
        #pragma unroll
        for (int q = 0; q < 2; ++q) {
            const int c = nt * 8 + lm4 * 2 + q;
            const float b2c = sF[F_B2 + c];
            const float w3a = sF[F_W3 + c];
            const float w3b = sF[F_W3 + 64 + c];
            float h = fmaxf(C[nt][q] + b2c, 0.f);
            o00 = fmaf(w3a, h, o00);
            o01 = fmaf(w3b, h, o01);
            h = fmaxf(C[nt][2 + q] + b2c, 0.f);
            o10 = fmaf(w3a, h, o10);
            o11 = fmaf(w3b, h, o11);
        }
    }
    o00 += __shfl_xor_sync(0xffffffffu, o00, 1);
    o00 += __shfl_xor_sync(0xffffffffu, o00, 2);
    o01 += __shfl_xor_sync(0xffffffffu, o01, 1);
    o01 += __shfl_xor_sync(0xffffffffu, o01, 2);
    o10 += __shfl_xor_sync(0xffffffffu, o10, 1);
    o10 += __shfl_xor_sync(0xffffffffu, o10, 2);
    o11 += __shfl_xor_sync(0xffffffffu, o11, 1);
    o11 += __shfl_xor_sync(0xffffffffu, o11, 2);

    if (lm4 == 0) {
        const float bb30 = sF[F_B3 + 0], bb31 = sF[F_B3 + 1];
        #pragma unroll
        for (int e = 0; e < 2; ++e) {
            const int row = r0 + 8 * e;
            const int sl  = row >> 6;
            const int g   = row & 63;
            const int sO  = blockIdx.x * 2 + sl;
            if (g < 63 && sO < Bn) {
                const float v0 = (e == 0) ? o00 : o10;
                const float v1 = (e == 0) ? o01 : o11;
                out[sO * 126 + g]      = v0 + bb30;
                out[sO * 126 + 63 + g] = v1 + bb31;
            }
        }
    }
}

extern "C" void kernel_launch(void* const* d_in, const int* in_sizes, int n_in,
                              void* d_out, int out_size) {
    const float* x    = (const float*)d_in[0];
    const int*   adj  = (const int*)  d_in[1];
    const float* ctx  = (const float*)d_in[2];
    const float* gcnW = (const float*)d_in[3];
    const float* gcnB = (const float*)d_in[4];
    const float* ctxW = (const float*)d_in[5];
    const float* ctxB = (const float*)d_in[6];
    const float* W1   = (const float*)d_in[7];
    const float* b1   = (const float*)d_in[8];
    const float* W2   = (const float*)d_in[9];
    const float* b2   = (const float*)d_in[10];
    const float* W3   = (const float*)d_in[11];
    const float* b3   = (const float*)d_in[12];
    float* outp = (float*)d_out;

    int Bn = in_sizes[0] / 63;
    int grid = (Bn + 1) / 2;
    car_mma2_kernel<<<grid, 256>>>(x, adj, ctx, gcnW, gcnB, ctxW, ctxB,
                                   W1, b1, W2, b2, W3, b3, outp, Bn);
}

// round 6
// speedup vs baseline: 2.1187x; 1.2525x over previous
#include <cuda_runtime.h>
#include <cuda_bf16.h>
#include <cstdint>

// ============================================================
// ldmatrix(B only) + mma.sync bf16 3-term split; A fragments built in registers.
// CTA = 256 threads, 2 samples (M=128 rows, 126 valid), 8 warps x 16 rows.
// zp/cp computed cooperatively once per row (no lm4-quad redundancy).
// ============================================================

__device__ __forceinline__ uint32_t smem_u32(const void* p) {
    uint32_t a;
    asm("{ .reg .u64 t; cvta.to.shared.u64 t, %1; cvt.u32.u64 %0, t; }" : "=r"(a) : "l"(p));
    return a;
}

__device__ __forceinline__ void ldsm4(uint32_t r[4], uint32_t addr) {
    asm volatile("ldmatrix.sync.aligned.m8n8.x4.shared.b16 {%0,%1,%2,%3}, [%4];"
                 : "=r"(r[0]), "=r"(r[1]), "=r"(r[2]), "=r"(r[3]) : "r"(addr));
}

__device__ __forceinline__ void mma16816(float c[4], const uint32_t a[4],
                                          uint32_t b0, uint32_t b1) {
    asm volatile("mma.sync.aligned.m16n8k16.row.col.f32.bf16.bf16.f32 "
                 "{%0,%1,%2,%3}, {%4,%5,%6,%7}, {%8,%9}, {%0,%1,%2,%3};"
                 : "+f"(c[0]), "+f"(c[1]), "+f"(c[2]), "+f"(c[3])
                 : "r"(a[0]), "r"(a[1]), "r"(a[2]), "r"(a[3]), "r"(b0), "r"(b1));
}

__device__ __forceinline__ void split_pack(float a, float b, uint32_t& hi, uint32_t& lo) {
    __nv_bfloat16 ah = __float2bfloat16(a);
    __nv_bfloat16 bh = __float2bfloat16(b);
    __nv_bfloat162 hp; hp.x = ah; hp.y = bh;
    __nv_bfloat162 lp = __floats2bfloat162_rn(a - __bfloat162float(ah),
                                              b - __bfloat162float(bh));
    hi = *reinterpret_cast<uint32_t*>(&hp);
    lo = *reinterpret_cast<uint32_t*>(&lp);
}

// triu(9) index tables
__constant__ unsigned char c_iu_i[45] = {
    0,0,0,0,0,0,0,0,0, 1,1,1,1,1,1,1,1, 2,2,2,2,2,2,2,
    3,3,3,3,3,3, 4,4,4,4,4, 5,5,5,5, 6,6,6, 7,7, 8};
__constant__ unsigned char c_iu_j[45] = {
    0,1,2,3,4,5,6,7,8, 1,2,3,4,5,6,7,8, 2,3,4,5,6,7,8,
    3,4,5,6,7,8, 4,5,6,7,8, 5,6,7,8, 6,7,8, 7,8, 8};

#define LDAB 72   // bf16 row stride for B tiles (144 B)

// float misc region offsets
#define F_CTXW 0       // 2835
#define F_W1   2835    // 128
#define F_B1   2963    // 64
#define F_B2   3027    // 64
#define F_W3   3091    // 128
#define F_GW   3219    // 49
#define F_GB   3268    // 7
#define F_CB   3275    // 63
#define F_B3   3338    // 2
#define F_X    3340    // 2*63
#define F_Y    3466    // 2*63
#define F_ADJ  3592    // 2*81
#define F_D    3754    // 2*9
#define F_CTX  3772    // 2*45
#define F_ZP   3862    // 128
#define F_CP   3990    // 128
#define F_TOTAL 4118

__global__ __launch_bounds__(256, 3)
void car_mma3_kernel(const float* __restrict__ x,      // (B,1,9,7)
                     const int*   __restrict__ adj,    // (B,45)
                     const float* __restrict__ ctx,    // (B,1,9,5)
                     const float* __restrict__ gcnW,   // (7,7)
                     const float* __restrict__ gcnB,   // (7,)
                     const float* __restrict__ ctxW,   // (45,63)
                     const float* __restrict__ ctxB,   // (63,)
                     const float* __restrict__ W1,     // (64,2)
                     const float* __restrict__ b1,     // (64,)
                     const float* __restrict__ W2,     // (64,64)
                     const float* __restrict__ b2,     // (64,)
                     const float* __restrict__ W3,     // (2,64)
                     const float* __restrict__ b3,     // (2,)
                     float* __restrict__ out,          // (B,2,9,7)
                     int Bn)
{
    __shared__ __align__(16) __nv_bfloat16 sBhi[64 * LDAB];
    __shared__ __align__(16) __nv_bfloat16 sBlo[64 * LDAB];
    __shared__ float sF[F_TOTAL];

    const int tid  = threadIdx.x;
    const int wid  = tid >> 5;
    const int lane = tid & 31;

    // ---- phase 1: weights -> SMEM; W2 -> bf16 hi/lo tiles ----
    for (int i = tid; i < 4096; i += 256) {
        float w = W2[i];                 // W2[n=o][k=c], k contiguous
        __nv_bfloat16 hi = __float2bfloat16(w);
        __nv_bfloat16 lo = __float2bfloat16(w - __bfloat162float(hi));
        int n = i >> 6, k = i & 63;
        sBhi[n * LDAB + k] = hi;
        sBlo[n * LDAB + k] = lo;
    }
    for (int i = tid; i < 2835; i += 256) sF[F_CTXW + i] = ctxW[i];
    if (tid < 128) { sF[F_W1 + tid] = W1[tid]; sF[F_W3 + tid] = W3[tid]; }
    if (tid < 64)  { sF[F_B1 + tid] = b1[tid]; sF[F_B2 + tid] = b2[tid]; }
    if (tid < 49)  sF[F_GW + tid] = gcnW[tid];
    if (tid < 7)   sF[F_GB + tid] = gcnB[tid];
    if (tid < 63)  sF[F_CB + tid] = ctxB[tid];
    if (tid < 2)   sF[F_B3 + tid] = b3[tid];

    // per-sample staging: 2 samples / CTA
    const int grp   = tid >> 7;      // 0..1
    const int inner = tid & 127;
    const int sG    = blockIdx.x * 2 + grp;
    const bool svalid = (sG < Bn);
    if (inner < 81) sF[F_ADJ + grp * 81 + inner] = 0.f;
    if (inner < 63) sF[F_X + grp * 63 + inner] = svalid ? x[sG * 63 + inner] : 0.f;
    if (inner < 45) sF[F_CTX + grp * 45 + inner] = svalid ? ctx[sG * 45 + inner] : 0.f;
    __syncthreads();

    // ---- phase 2: adjacency fill + y = x @ gcnW ----
    if (svalid && inner < 45) {
        int i = c_iu_i[inner], j = c_iu_j[inner];
        sF[F_ADJ + grp * 81 + i * 9 + j] = (adj[sG * 45 + inner] > 0) ? 1.f : 0.f;
    }
    if (inner < 63) {
        int n = inner / 7, f = inner % 7;
        float acc = 0.f;
        #pragma unroll
        for (int k = 0; k < 7; ++k)
            acc = fmaf(sF[F_X + grp * 63 + n * 7 + k], sF[F_GW + k * 7 + f], acc);
        sF[F_Y + grp * 63 + inner] = acc;
    }
    __syncthreads();

    // ---- phase 3: diag=1, degree norm ----
    if (inner < 9) {
        sF[F_ADJ + grp * 81 + inner * 9 + inner] = 1.f;
        float rs = 0.f;
        #pragma unroll
        for (int m = 0; m < 9; ++m) rs += sF[F_ADJ + grp * 81 + inner * 9 + m];
        sF[F_D + grp * 9 + inner] = rsqrtf(fmaxf(rs, 1.f));
    }
    __syncthreads();

    // ---- phase 4a: cooperative per-row zp/cp (once per row) ----
    {
        const int row = tid & 127;
        const int sl  = row >> 6;
        const int g   = row & 63;
        const bool pv = (g < 63) && (blockIdx.x * 2 + sl < Bn);
        if (tid < 128) {
            // cp[row] = relu(ctx . ctxW[:,g] + ctxB[g])
            float c = 0.f;
            if (pv) {
                float a0 = 0.f, a1 = 0.f, a2 = 0.f, a3 = 0.f;
                const float* cw = sF + F_CTXW + g;
                const float* cx = sF + F_CTX + sl * 45;
                #pragma unroll
                for (int i = 0; i < 44; i += 4) {
                    a0 = fmaf(cx[i],     cw[i * 63],       a0);
                    a1 = fmaf(cx[i + 1], cw[(i + 1) * 63], a1);
                    a2 = fmaf(cx[i + 2], cw[(i + 2) * 63], a2);
                    a3 = fmaf(cx[i + 3], cw[(i + 3) * 63], a3);
                }
                a0 = fmaf(cx[44], cw[44 * 63], a0);
                c = fmaxf(sF[F_CB + g] + ((a0 + a1) + (a2 + a3)), 0.f);
            }
            sF[F_CP + row] = c;
        } else {
            // zp[row] = d[n] * sum_m A[n,m] d[m] y[m,f] + gcnB[f]
            float z = 0.f;
            if (pv) {
                const int n = g / 7, f = g % 7;
                float acc = 0.f;
                #pragma unroll
                for (int m = 0; m < 9; ++m)
                    acc = fmaf(sF[F_ADJ + sl * 81 + n * 9 + m] * sF[F_D + sl * 9 + m],
                               sF[F_Y + sl * 63 + m * 7 + f], acc);
                z = fmaf(acc, sF[F_D + sl * 9 + n], sF[F_GB + f]);
            }
            sF[F_ZP + row] = z;
        }
    }
    __syncthreads();

    // ---- phase 4b: lanes fetch their 2 rows' (zp, cp) ----
    const int l4  = lane >> 2;
    const int lm4 = lane & 3;
    const int r0  = wid * 16 + l4;     // rows r0, r0+8 within M=128

    float zp[2], cp[2];
    zp[0] = sF[F_ZP + r0];     zp[1] = sF[F_ZP + r0 + 8];
    cp[0] = sF[F_CP + r0];     cp[1] = sF[F_CP + r0 + 8];

    // ---- phase 5: k-loop, A fragments built in registers, HMMA ----
    float C[8][4];
    #pragma unroll
    for (int n = 0; n < 8; ++n)
        #pragma unroll
        for (int q = 0; q < 4; ++q) C[n][q] = 0.f;

    const uint32_t sub = (uint32_t)(lane >> 3);
    const uint32_t j7  = (uint32_t)(lane & 7);
    const uint32_t bOff = ((sub >> 1) * 8 + j7) * (LDAB * 2) + (sub & 1) * 16;
    const uint32_t bHiBase = smem_u32(sBhi) + bOff;
    const uint32_t bLoBase = smem_u32(sBlo) + bOff;

    #pragma unroll
    for (int ks = 0; ks < 4; ++ks) {
        // A fragments: rows r0, r0+8; cols cb,cb+1 (pair0), cb+8,cb+9 (pair1)
        uint32_t Ahi[4], Alo[4];
        const int cb = lm4 * 2 + ks * 16;
        #pragma unroll
        for (int p = 0; p < 2; ++p) {
            const int c = cb + p * 8;
            const float w00 = sF[F_W1 + 2 * c],     w01 = sF[F_W1 + 2 * c + 1];
            const float w10 = sF[F_W1 + 2 * c + 2], w11 = sF[F_W1 + 2 * c + 3];
            const float bb0 = sF[F_B1 + c],         bb1 = sF[F_B1 + c + 1];
            #pragma unroll
            for (int e = 0; e < 2; ++e) {
                float v0 = fmaxf(fmaf(zp[e], w00, fmaf(cp[e], w01, bb0)), 0.f);
                float v1 = fmaxf(fmaf(zp[e], w10, fmaf(cp[e], w11, bb1)), 0.f);
                split_pack(v0, v1, Ahi[p * 2 + e], Alo[p * 2 + e]);
            }
        }

        const uint32_t kB = (uint32_t)ks * 32;  // 16 bf16 = 32 bytes
        #pragma unroll
        for (int nh = 0; nh < 2; ++nh) {
            uint32_t bh[2][4], bl[2][4];
            ldsm4(bh[0], bHiBase + (uint32_t)(nh * 32)      * (LDAB * 2) + kB);
            ldsm4(bh[1], bHiBase + (uint32_t)(nh * 32 + 16) * (LDAB * 2) + kB);
            ldsm4(bl[0], bLoBase + (uint32_t)(nh * 32)      * (LDAB * 2) + kB);
            ldsm4(bl[1], bLoBase + (uint32_t)(nh * 32 + 16) * (LDAB * 2) + kB);
            #pragma unroll
            for (int t = 0; t < 4; ++t) {
                const int nt = nh * 4 + t;
                const uint32_t b0h = bh[t >> 1][(t & 1) * 2];
                const uint32_t b1h = bh[t >> 1][(t & 1) * 2 + 1];
                const uint32_t b0l = bl[t >> 1][(t & 1) * 2];
                const uint32_t b1l = bl[t >> 1][(t & 1) * 2 + 1];
                mma16816(C[nt], Ahi, b0h, b1h);   // hi*hi
                mma16816(C[nt], Ahi, b0l, b1l);   // hi*lo
                mma16816(C[nt], Alo, b0h, b1h);   // lo*hi
            }
        }
    }

    // ---- phase 6: in-register epilogue: relu+b2, W3 dot, quad reduce ----
    float o00 = 0.f, o01 = 0.f, o10 = 0.f, o11 = 0.f;  // (row e, out channel)
    #pragma unroll
    for (int nt = 0; nt < 8; ++nt) {
        #pragma unroll
        for (int q = 0; q < 2; ++q) {
            const int c = nt * 8 + lm4 * 2 + q;
            const float b2c = sF[F_B2 + c];
            const float w3a = sF[F_W3 + c];
            const float w3b = sF[F_W3 + 64 + c];
            float h = fmaxf(C[nt][q] + b2c, 0.f);
            o00 = fmaf(w3a, h, o00);
            o01 = fmaf(w3b, h, o01);
            h = fmaxf(C[nt][2 + q] + b2c, 0.f);
            o10 = fmaf(w3a, h, o10);
            o11 = fmaf(w3b, h, o11);
        }
    }
    o00 += __shfl_xor_sync(0xffffffffu, o00, 1);
    o00 += __shfl_xor_sync(0xffffffffu, o00, 2);
    o01 += __shfl_xor_sync(0xffffffffu, o01, 1);
    o01 += __shfl_xor_sync(0xffffffffu, o01, 2);
    o10 += __shfl_xor_sync(0xffffffffu, o10, 1);
    o10 += __shfl_xor_sync(0xffffffffu, o10, 2);
    o11 += __shfl_xor_sync(0xffffffffu, o11, 1);
    o11 += __shfl_xor_sync(0xffffffffu, o11, 2);

    if (lm4 == 0) {
        const float bb30 = sF[F_B3 + 0], bb31 = sF[F_B3 + 1];
        #pragma unroll
        for (int e = 0; e < 2; ++e) {
            const int row = r0 + 8 * e;
            const int sl  = row >> 6;
            const int g   = row & 63;
            const int sO  = blockIdx.x * 2 + sl;
            if (g < 63 && sO < Bn) {
                const float v0 = (e == 0) ? o00 : o10;
                const float v1 = (e == 0) ? o01 : o11;
                out[sO * 126 + g]      = v0 + bb30;
                out[sO * 126 + 63 + g] = v1 + bb31;
            }
        }
    }
}

extern "C" void kernel_launch(void* const* d_in, const int* in_sizes, int n_in,
                              void* d_out, int out_size) {
    const float* x    = (const float*)d_in[0];
    const int*   adj  = (const int*)  d_in[1];
    const float* ctx  = (const float*)d_in[2];
    const float* gcnW = (const float*)d_in[3];
    const float* gcnB = (const float*)d_in[4];
    const float* ctxW = (const float*)d_in[5];
    const float* ctxB = (const float*)d_in[6];
    const float* W1   = (const float*)d_in[7];
    const float* b1   = (const float*)d_in[8];
    const float* W2   = (const float*)d_in[9];
    const float* b2   = (const float*)d_in[10];
    const float* W3   = (const float*)d_in[11];
    const float* b3   = (const float*)d_in[12];
    float* outp = (float*)d_out;

    int Bn = in_sizes[0] / 63;
    int grid = (Bn + 1) / 2;
    car_mma3_kernel<<<grid, 256>>>(x, adj, ctx, gcnW, gcnB, ctxW, ctxB,
                                   W1, b1, W2, b2, W3, b3, outp, Bn);
}

// round 7
// speedup vs baseline: 2.4479x; 1.1553x over previous
#include <cuda_runtime.h>
#include <cuda_bf16.h>
#include <cstdint>

// ============================================================
// ldmatrix(B only) + mma.sync bf16 3-term split; A fragments built in registers.
// CTA = 256 threads, 2 samples (M=128 rows), 8 warps x 16 rows.
// W2 hi/lo pack precomputed once by a tiny prepack kernel into device globals.
// ============================================================

#define LDAB 72   // bf16 row stride for B tiles (144 B)
#define BPK_U4 (64 * LDAB * 2 / 16)   // 576 uint4 per tile

__device__ uint4 g_Bhi4[BPK_U4];
__device__ uint4 g_Blo4[BPK_U4];

__device__ __forceinline__ uint32_t smem_u32(const void* p) {
    uint32_t a;
    asm("{ .reg .u64 t; cvta.to.shared.u64 t, %1; cvt.u32.u64 %0, t; }" : "=r"(a) : "l"(p));
    return a;
}

__device__ __forceinline__ void ldsm4(uint32_t r[4], uint32_t addr) {
    asm volatile("ldmatrix.sync.aligned.m8n8.x4.shared.b16 {%0,%1,%2,%3}, [%4];"
                 : "=r"(r[0]), "=r"(r[1]), "=r"(r[2]), "=r"(r[3]) : "r"(addr));
}

__device__ __forceinline__ void mma16816(float c[4], const uint32_t a[4],
                                          uint32_t b0, uint32_t b1) {
    asm volatile("mma.sync.aligned.m16n8k16.row.col.f32.bf16.bf16.f32 "
                 "{%0,%1,%2,%3}, {%4,%5,%6,%7}, {%8,%9}, {%0,%1,%2,%3};"
                 : "+f"(c[0]), "+f"(c[1]), "+f"(c[2]), "+f"(c[3])
                 : "r"(a[0]), "r"(a[1]), "r"(a[2]), "r"(a[3]), "r"(b0), "r"(b1));
}

__device__ __forceinline__ void split_pack(float a, float b, uint32_t& hi, uint32_t& lo) {
    __nv_bfloat16 ah = __float2bfloat16(a);
    __nv_bfloat16 bh = __float2bfloat16(b);
    __nv_bfloat162 hp; hp.x = ah; hp.y = bh;
    __nv_bfloat162 lp = __floats2bfloat162_rn(a - __bfloat162float(ah),
                                              b - __bfloat162float(bh));
    hi = *reinterpret_cast<uint32_t*>(&hp);
    lo = *reinterpret_cast<uint32_t*>(&lp);
}

// triu(9) index tables
__constant__ unsigned char c_iu_i[45] = {
    0,0,0,0,0,0,0,0,0, 1,1,1,1,1,1,1,1, 2,2,2,2,2,2,2,
    3,3,3,3,3,3, 4,4,4,4,4, 5,5,5,5, 6,6,6, 7,7, 8};
__constant__ unsigned char c_iu_j[45] = {
    0,1,2,3,4,5,6,7,8, 1,2,3,4,5,6,7,8, 2,3,4,5,6,7,8,
    3,4,5,6,7,8, 4,5,6,7,8, 5,6,7,8, 6,7,8, 7,8, 8};

// float misc region offsets
#define F_CTXW 0       // 2835
#define F_W1   2835    // 128
#define F_B1   2963    // 64
#define F_B2   3027    // 64
#define F_W3   3091    // 128
#define F_GW   3219    // 49
#define F_GB   3268    // 7
#define F_CB   3275    // 63
#define F_B3   3338    // 2
#define F_X    3340    // 2*63
#define F_Y    3466    // 2*63
#define F_ADJ  3592    // 2*81
#define F_D    3754    // 2*9
#define F_CTX  3772    // 2*45
#define F_ZP   3862    // 128
#define F_CP   3990    // 128
#define F_TOTAL 4118

// ---- one-time W2 -> bf16 hi/lo pack (padded [64][72], pad zeroed) ----
__global__ void prepack_kernel(const float* __restrict__ W2) {
    int i = blockIdx.x * blockDim.x + threadIdx.x;
    if (i < 64 * LDAB) {
        int n = i / LDAB, k = i % LDAB;
        __nv_bfloat16 hi = __float2bfloat16(0.f);
        __nv_bfloat16 lo = hi;
        if (k < 64) {
            float w = W2[n * 64 + k];
            hi = __float2bfloat16(w);
            lo = __float2bfloat16(w - __bfloat162float(hi));
        }
        reinterpret_cast<__nv_bfloat16*>(g_Bhi4)[i] = hi;
        reinterpret_cast<__nv_bfloat16*>(g_Blo4)[i] = lo;
    }
}

__global__ __launch_bounds__(256, 3)
void car_mma4_kernel(const float* __restrict__ x,      // (B,1,9,7)
                     const int*   __restrict__ adj,    // (B,45)
                     const float* __restrict__ ctx,    // (B,1,9,5)
                     const float* __restrict__ gcnW,   // (7,7)
                     const float* __restrict__ gcnB,   // (7,)
                     const float* __restrict__ ctxW,   // (45,63)
                     const float* __restrict__ ctxB,   // (63,)
                     const float* __restrict__ W1,     // (64,2)
                     const float* __restrict__ b1,     // (64,)
                     const float* __restrict__ b2,     // (64,)
                     const float* __restrict__ W3,     // (2,64)
                     const float* __restrict__ b3,     // (2,)
                     float* __restrict__ out,          // (B,2,9,7)
                     int Bn)
{
    __shared__ __align__(16) __nv_bfloat16 sBhi[64 * LDAB];
    __shared__ __align__(16) __nv_bfloat16 sBlo[64 * LDAB];
    __shared__ __align__(16) float sF[F_TOTAL];

    const int tid  = threadIdx.x;
    const int wid  = tid >> 5;
    const int lane = tid & 31;

    // ---- phase 1: bulk copies of prepacked weights ----
    {
        uint4* dh = reinterpret_cast<uint4*>(sBhi);
        uint4* dl = reinterpret_cast<uint4*>(sBlo);
        #pragma unroll
        for (int i = tid; i < BPK_U4; i += 256) { dh[i] = g_Bhi4[i]; dl[i] = g_Blo4[i]; }
    }
    {
        const float4* s4 = reinterpret_cast<const float4*>(ctxW);
        float4* d4 = reinterpret_cast<float4*>(sF + F_CTXW);
        for (int i = tid; i < 708; i += 256) d4[i] = s4[i];
        if (tid < 3) sF[F_CTXW + 2832 + tid] = ctxW[2832 + tid];
    }
    if (tid < 128) { sF[F_W1 + tid] = W1[tid]; sF[F_W3 + tid] = W3[tid]; }
    if (tid < 64)  { sF[F_B1 + tid] = b1[tid]; sF[F_B2 + tid] = b2[tid]; }
    if (tid < 49)  sF[F_GW + tid] = gcnW[tid];
    if (tid < 7)   sF[F_GB + tid] = gcnB[tid];
    if (tid < 63)  sF[F_CB + tid] = ctxB[tid];
    if (tid < 2)   sF[F_B3 + tid] = b3[tid];

    // per-sample staging: 2 samples / CTA
    const int grp   = tid >> 7;      // 0..1
    const int inner = tid & 127;
    const int sG    = blockIdx.x * 2 + grp;
    const bool svalid = (sG < Bn);
    if (inner < 81) sF[F_ADJ + grp * 81 + inner] = 0.f;
    if (inner < 63) sF[F_X + grp * 63 + inner] = svalid ? x[sG * 63 + inner] : 0.f;
    if (inner < 45) sF[F_CTX + grp * 45 + inner] = svalid ? ctx[sG * 45 + inner] : 0.f;
    __syncthreads();

    // ---- phase 2: adjacency fill + y = x @ gcnW ----
    if (svalid && inner < 45) {
        int i = c_iu_i[inner], j = c_iu_j[inner];
        sF[F_ADJ + grp * 81 + i * 9 + j] = (adj[sG * 45 + inner] > 0) ? 1.f : 0.f;
    }
    if (inner < 63) {
        int n = inner / 7, f = inner % 7;
        float acc = 0.f;
        #pragma unroll
        for (int k = 0; k < 7; ++k)
            acc = fmaf(sF[F_X + grp * 63 + n * 7 + k], sF[F_GW + k * 7 + f], acc);
        sF[F_Y + grp * 63 + inner] = acc;
    }
    __syncthreads();

    // ---- phase 3: diag=1, degree norm ----
    if (inner < 9) {
        sF[F_ADJ + grp * 81 + inner * 9 + inner] = 1.f;
        float rs = 0.f;
        #pragma unroll
        for (int m = 0; m < 9; ++m) rs += sF[F_ADJ + grp * 81 + inner * 9 + m];
        sF[F_D + grp * 9 + inner] = rsqrtf(fmaxf(rs, 1.f));
    }
    __syncthreads();

    // ---- phase 4a: cooperative per-row zp/cp (once per row) ----
    {
        const int row = tid & 127;
        const int sl  = row >> 6;
        const int g   = row & 63;
        const bool pv = (g < 63) && (blockIdx.x * 2 + sl < Bn);
        if (tid < 128) {
            float c = 0.f;
            if (pv) {
                float a0 = 0.f, a1 = 0.f, a2 = 0.f, a3 = 0.f;
                const float* cw = sF + F_CTXW + g;
                const float* cx = sF + F_CTX + sl * 45;
                #pragma unroll
                for (int i = 0; i < 44; i += 4) {
                    a0 = fmaf(cx[i],     cw[i * 63],       a0);
                    a1 = fmaf(cx[i + 1], cw[(i + 1) * 63], a1);
                    a2 = fmaf(cx[i + 2], cw[(i + 2) * 63], a2);
                    a3 = fmaf(cx[i + 3], cw[(i + 3) * 63], a3);
                }
                a0 = fmaf(cx[44], cw[44 * 63], a0);
                c = fmaxf(sF[F_CB + g] + ((a0 + a1) + (a2 + a3)), 0.f);
            }
            sF[F_CP + row] = c;
        } else {
            float z = 0.f;
            if (pv) {
                const int n = g / 7, f = g % 7;
                float acc = 0.f;
                #pragma unroll
                for (int m = 0; m < 9; ++m)
                    acc = fmaf(sF[F_ADJ + sl * 81 + n * 9 + m] * sF[F_D + sl * 9 + m],
                               sF[F_Y + sl * 63 + m * 7 + f], acc);
                z = fmaf(acc, sF[F_D + sl * 9 + n], sF[F_GB + f]);
            }
            sF[F_ZP + row] = z;
        }
    }
    __syncthreads();

    // ---- phase 4b: lanes fetch their 2 rows' (zp, cp) ----
    const int l4  = lane >> 2;
    const int lm4 = lane & 3;
    const int r0  = wid * 16 + l4;     // rows r0, r0+8 within M=128

    float zp[2], cp[2];
    zp[0] = sF[F_ZP + r0];     zp[1] = sF[F_ZP + r0 + 8];
    cp[0] = sF[F_CP + r0];     cp[1] = sF[F_CP + r0 + 8];

    // ---- phase 5: k-loop, A fragments built in registers, HMMA ----
    float C[8][4];
    #pragma unroll
    for (int n = 0; n < 8; ++n)
        #pragma unroll
        for (int q = 0; q < 4; ++q) C[n][q] = 0.f;

    const uint32_t sub = (uint32_t)(lane >> 3);
    const uint32_t j7  = (uint32_t)(lane & 7);
    const uint32_t bOff = ((sub >> 1) * 8 + j7) * (LDAB * 2) + (sub & 1) * 16;
    const uint32_t bHiBase = smem_u32(sBhi) + bOff;
    const uint32_t bLoBase = smem_u32(sBlo) + bOff;

    #pragma unroll
    for (int ks = 0; ks < 4; ++ks) {
        uint32_t Ahi[4], Alo[4];
        const int cb = lm4 * 2 + ks * 16;
        #pragma unroll
        for (int p = 0; p < 2; ++p) {
            const int c = cb + p * 8;
            const float w00 = sF[F_W1 + 2 * c],     w01 = sF[F_W1 + 2 * c + 1];
            const float w10 = sF[F_W1 + 2 * c + 2], w11 = sF[F_W1 + 2 * c + 3];
            const float bb0 = sF[F_B1 + c],         bb1 = sF[F_B1 + c + 1];
            #pragma unroll
            for (int e = 0; e < 2; ++e) {
                float v0 = fmaxf(fmaf(zp[e], w00, fmaf(cp[e], w01, bb0)), 0.f);
                float v1 = fmaxf(fmaf(zp[e], w10, fmaf(cp[e], w11, bb1)), 0.f);
                split_pack(v0, v1, Ahi[p * 2 + e], Alo[p * 2 + e]);
            }
        }

        const uint32_t kB = (uint32_t)ks * 32;
        #pragma unroll
        for (int nh = 0; nh < 2; ++nh) {
            uint32_t bh[2][4], bl[2][4];
            ldsm4(bh[0], bHiBase + (uint32_t)(nh * 32)      * (LDAB * 2) + kB);
            ldsm4(bh[1], bHiBase + (uint32_t)(nh * 32 + 16) * (LDAB * 2) + kB);
            ldsm4(bl[0], bLoBase + (uint32_t)(nh * 32)      * (LDAB * 2) + kB);
            ldsm4(bl[1], bLoBase + (uint32_t)(nh * 32 + 16) * (LDAB * 2) + kB);
            #pragma unroll
            for (int t = 0; t < 4; ++t) {
                const int nt = nh * 4 + t;
                const uint32_t b0h = bh[t >> 1][(t & 1) * 2];
                const uint32_t b1h = bh[t >> 1][(t & 1) * 2 + 1];
                const uint32_t b0l = bl[t >> 1][(t & 1) * 2];
                const uint32_t b1l = bl[t >> 1][(t & 1) * 2 + 1];
                mma16816(C[nt], Ahi, b0h, b1h);   // hi*hi
                mma16816(C[nt], Ahi, b0l, b1l);   // hi*lo
                mma16816(C[nt], Alo, b0h, b1h);   // lo*hi
            }
        }
    }

    // ---- phase 6: in-register epilogue: relu+b2, W3 dot, quad reduce ----
    float o00 = 0.f, o01 = 0.f, o10 = 0.f, o11 = 0.f;
    #pragma unroll
    for (int nt = 0; nt < 8; ++nt) {
        #pragma unroll
        for (int q = 0; q < 2; ++q) {
            const int c = nt * 8 + lm4 * 2 + q;
            const float b2c = sF[F_B2 + c];
            const float w3a = sF[F_W3 + c];
            const float w3b = sF[F_W3 + 64 + c];
            float h = fmaxf(C[nt][q] + b2c, 0.f);
            o00 = fmaf(w3a, h, o00);
            o01 = fmaf(w3b, h, o01);
            h = fmaxf(C[nt][2 + q] + b2c, 0.f);
            o10 = fmaf(w3a, h, o10);
            o11 = fmaf(w3b, h, o11);
        }
    }
    o00 += __shfl_xor_sync(0xffffffffu, o00, 1);
    o00 += __shfl_xor_sync(0xffffffffu, o00, 2);
    o01 += __shfl_xor_sync(0xffffffffu, o01, 1);
    o01 += __shfl_xor_sync(0xffffffffu, o01, 2);
    o10 += __shfl_xor_sync(0xffffffffu, o10, 1);
    o10 += __shfl_xor_sync(0xffffffffu, o10, 2);
    o11 += __shfl_xor_sync(0xffffffffu, o11, 1);
    o11 += __shfl_xor_sync(0xffffffffu, o11, 2);

    if (lm4 == 0) {
        const float bb30 = sF[F_B3 + 0], bb31 = sF[F_B3 + 1];
        #pragma unroll
        for (int e = 0; e < 2; ++e) {
            const int row = r0 + 8 * e;
            const int sl  = row >> 6;
            const int g   = row & 63;
            const int sO  = blockIdx.x * 2 + sl;
            if (g < 63 && sO < Bn) {
                const float v0 = (e == 0) ? o00 : o10;
                const float v1 = (e == 0) ? o01 : o11;
                out[sO * 126 + g]      = v0 + bb30;
                out[sO * 126 + 63 + g] = v1 + bb31;
            }
        }
    }
}

extern "C" void kernel_launch(void* const* d_in, const int* in_sizes, int n_in,
                              void* d_out, int out_size) {
    const float* x    = (const float*)d_in[0];
    const int*   adj  = (const int*)  d_in[1];
    const float* ctx  = (const float*)d_in[2];
    const float* gcnW = (const float*)d_in[3];
    const float* gcnB = (const float*)d_in[4];
    const float* ctxW = (const float*)d_in[5];
    const float* ctxB = (const float*)d_in[6];
    const float* W1   = (const float*)d_in[7];
    const float* b1   = (const float*)d_in[8];
    const float* W2   = (const float*)d_in[9];
    const float* b2   = (const float*)d_in[10];
    const float* W3   = (const float*)d_in[11];
    const float* b3   = (const float*)d_in[12];
    float* outp = (float*)d_out;

    prepack_kernel<<<18, 256>>>(W2);

    int Bn = in_sizes[0] / 63;
    int grid = (Bn + 1) / 2;
    car_mma4_kernel<<<grid, 256>>>(x, adj, ctx, gcnW, gcnB, ctxW, ctxB,
                                   W1, b1, b2, W3, b3, outp, Bn);
}